// round 4
// baseline (speedup 1.0000x reference)
#include <cuda_runtime.h>
#include <math.h>

// Device-global accumulators (no allocation allowed). Self-resetting across
// graph replays: the last block to finish reads, finalizes, and re-zeros.
__device__ double   g_sum   = 0.0;
__device__ unsigned g_count = 0u;

// ---------------------------------------------------------------------------
// Single fused kernel, explicitly batched for MLP:
//   transforms (6) -> addresses (6) -> 12 LDG.64 in flight -> distances -> reduce
// __launch_bounds__(256, 4): 64-reg budget so all loads stay in flight.
// ---------------------------------------------------------------------------
__global__ void __launch_bounds__(256, 4)
fused_kernel(const float* __restrict__ pts,
             const float* __restrict__ planes,
             const float* __restrict__ axes,
             const float* __restrict__ grid,
             const float* __restrict__ gmin,
             const float* __restrict__ gmax,
             float* __restrict__ out,
             int out_size, int N, int R)
{
    const float2* __restrict__ grid2 = (const float2*)grid;

    // --- Stage this block's 256 points (768 floats) via coalesced float4 ---
    __shared__ float s_pts[256 * 3];
    {
        int floatBase = blockIdx.x * 256 * 3;
        int totalF = 3 * N;
        if (threadIdx.x < 192) {
            int fi = floatBase + threadIdx.x * 4;
            float4 v;
            if (fi + 4 <= totalF) {
                v = __ldg((const float4*)(pts + fi));
            } else {
                v.x = (fi + 0 < totalF) ? __ldg(pts + fi + 0) : 0.f;
                v.y = (fi + 1 < totalF) ? __ldg(pts + fi + 1) : 0.f;
                v.z = (fi + 2 < totalF) ? __ldg(pts + fi + 2) : 0.f;
                v.w = (fi + 3 < totalF) ? __ldg(pts + fi + 3) : 0.f;
            }
            *(float4*)&s_pts[threadIdx.x * 4] = v;
        }
    }
    __syncthreads();

    int i = blockIdx.x * blockDim.x + threadIdx.x;

    float gx = __ldg(gmin), gy = __ldg(gmin + 1), gz = __ldg(gmin + 2);
    float sx = (float)(R - 1) / (__ldg(gmax)     - gx);
    float sy = (float)(R - 1) / (__ldg(gmax + 1) - gy);
    float sz = (float)(R - 1) / (__ldg(gmax + 2) - gz);
    unsigned strideY = (unsigned)(R * 3);
    unsigned strideX = strideY * (unsigned)R;
    int Rm1 = R - 1;

    float local = 0.f;

    if (i < N) {
        float px = s_pts[threadIdx.x * 3 + 0];
        float py = s_pts[threadIdx.x * 3 + 1];
        float pz = s_pts[threadIdx.x * 3 + 2];

        // ---- Phase 1: all 6 transformed points ----
        float tx[6], ty[6], tz[6];

        #pragma unroll
        for (int k = 0; k < 3; k++) {
            float nx = __ldg(planes + k * 4);
            float ny = __ldg(planes + k * 4 + 1);
            float nz = __ldg(planes + k * 4 + 2);
            float d  = __ldg(planes + k * 4 + 3);
            float proj = px * nx + py * ny + pz * nz + d;
            tx[k] = px - 2.f * proj * nx;
            ty[k] = py - 2.f * proj * ny;
            tz[k] = pz - 2.f * proj * nz;
        }

        #pragma unroll
        for (int k = 0; k < 3; k++) {
            float w = __ldg(axes + k * 4);
            float x = __ldg(axes + k * 4 + 1);
            float y = __ldg(axes + k * 4 + 2);
            float z = __ldg(axes + k * 4 + 3);
            float tw = -x * px - y * py - z * pz;
            float qx =  w * px + y * pz - z * py;
            float qy =  w * py - x * pz + z * px;
            float qz =  w * pz + x * py - y * px;
            tx[3 + k] = -tw * x + qx * w - qy * z + qz * y;
            ty[3 + k] = -tw * y + qx * z + qy * w - qz * x;
            tz[3 + k] = -tw * z - qx * y + qy * x + qz * w;
        }

        // ---- Phase 2: all 6 gather addresses ----
        unsigned h[6];
        bool odd[6];
        #pragma unroll
        for (int k = 0; k < 6; k++) {
            int ix = __float2int_rn((tx[k] - gx) * sx);   // round-half-even = jnp.round
            int iy = __float2int_rn((ty[k] - gy) * sy);
            int iz = __float2int_rn((tz[k] - gz) * sz);
            ix = min(max(ix, 0), Rm1);
            iy = min(max(iy, 0), Rm1);
            iz = min(max(iz, 0), Rm1);
            unsigned off = (unsigned)ix * strideX + (unsigned)iy * strideY + (unsigned)iz * 3u;
            h[k]   = off >> 1;
            odd[k] = (off & 1u) != 0u;
        }

        // ---- Phase 3: issue all 12 loads (front-batched, max MLP) ----
        float2 a[6], b[6];
        #pragma unroll
        for (int k = 0; k < 6; k++) {
            a[k] = __ldg(grid2 + h[k]);
            b[k] = __ldg(grid2 + h[k] + 1u);
        }

        // ---- Phase 4: distances ----
        #pragma unroll
        for (int k = 0; k < 6; k++) {
            float cx = odd[k] ? a[k].y : a[k].x;
            float cy = odd[k] ? b[k].x : a[k].y;
            float cz = odd[k] ? b[k].y : b[k].x;
            float dx = tx[k] - cx, dy = ty[k] - cy, dz = tz[k] - cz;
            local += sqrtf(fmaf(dx, dx, fmaf(dy, dy, dz * dz)));
        }
    }

    // Warp reduce
    #pragma unroll
    for (int off = 16; off > 0; off >>= 1)
        local += __shfl_down_sync(0xFFFFFFFFu, local, off);

    // Block reduce
    __shared__ float warp_sums[8];
    int lane = threadIdx.x & 31;
    int wid  = threadIdx.x >> 5;
    if (lane == 0) warp_sums[wid] = local;
    __syncthreads();

    __shared__ bool is_last;
    if (wid == 0) {
        float s = (lane < (blockDim.x >> 5)) ? warp_sums[lane] : 0.f;
        #pragma unroll
        for (int off = 4; off > 0; off >>= 1)
            s += __shfl_down_sync(0xFFFFFFFFu, s, off);
        if (lane == 0) {
            atomicAdd(&g_sum, (double)s);
            __threadfence();
            unsigned old = atomicInc(&g_count, gridDim.x - 1u);
            is_last = (old == gridDim.x - 1u);
        }
    }
    __syncthreads();

    // Last block finalizes: read total, compute regularizer, write out, reset.
    if (is_last && threadIdx.x == 0) {
        double total = atomicAdd(&g_sum, 0.0);  // atomic read
        g_sum = 0.0;                            // reset for next replay
        __threadfence();

        float n[3][3], v[3][3];
        #pragma unroll
        for (int r = 0; r < 3; r++) {
            #pragma unroll
            for (int c = 0; c < 3; c++)
                n[r][c] = __ldg(planes + r * 4 + c);
            float x = __ldg(axes + r * 4 + 1);
            float y = __ldg(axes + r * 4 + 2);
            float z = __ldg(axes + r * 4 + 3);
            float nrm = sqrtf(x * x + y * y + z * z);
            float inv = 1.f / fmaxf(nrm, 1e-12f);
            v[r][0] = x * inv; v[r][1] = y * inv; v[r][2] = z * inv;
        }
        float sumA2 = 0.f, sumB2 = 0.f;
        #pragma unroll
        for (int r = 0; r < 3; r++)
            #pragma unroll
            for (int c = 0; c < 3; c++) {
                float da = n[r][0] * n[c][0] + n[r][1] * n[c][1] + n[r][2] * n[c][2]
                         - (r == c ? 1.f : 0.f);
                float db = v[r][0] * v[c][0] + v[r][1] * v[c][1] + v[r][2] * v[c][2]
                         - (r == c ? 1.f : 0.f);
                sumA2 += da * da;
                sumB2 += db * db;
            }

        float loss_r = sumA2 + sumB2;
        float sd  = (float)(total / (double)N);
        float fin = sd + 25.0f * loss_r;
        out[0] = fin;
        if (out_size > 1) out[1] = sd;
        if (out_size > 2) out[2] = loss_r;
    }
}

// ---------------------------------------------------------------------------
extern "C" void kernel_launch(void* const* d_in, const int* in_sizes, int n_in,
                              void* d_out, int out_size)
{
    const float* planes = (const float*)d_in[0];   // (1,3,4)
    const float* axes   = (const float*)d_in[1];   // (1,3,4)
    const float* pts    = (const float*)d_in[2];   // (N,3)
    const float* grid   = (const float*)d_in[3];   // (R,R,R,3)
    const float* gmin   = (const float*)d_in[4];   // (3,)
    const float* gmax   = (const float*)d_in[5];   // (3,)

    int N = in_sizes[2] / 3;
    long gelems = (long)in_sizes[3] / 3;
    int R = (int)llrintf(cbrtf((float)gelems));

    int threads = 256;
    int blocks = (N + threads - 1) / threads;
    fused_kernel<<<blocks, threads>>>(pts, planes, axes, grid, gmin, gmax,
                                      (float*)d_out, out_size, N, R);
}

// round 5
// speedup vs baseline: 1.2150x; 1.2150x over previous
#include <cuda_runtime.h>
#include <math.h>

// Device-global accumulator. Starts at 0 (static init); finalize_kernel
// resets it to 0 after reading, so every graph replay sees 0. No prep kernel.
__device__ double g_sum = 0.0;

// ---------------------------------------------------------------------------
// Grid distance: nearest cell (round-half-even = jnp.round), integer clamp,
// gather 3 floats, return |tp - cp|.
// ---------------------------------------------------------------------------
__device__ __forceinline__ float grid_dist(float tx, float ty, float tz,
                                           const float* __restrict__ grid,
                                           float gx, float gy, float gz,
                                           float sx, float sy, float sz,
                                           int Rm1, unsigned strideX, unsigned strideY)
{
    int ix = __float2int_rn((tx - gx) * sx);
    int iy = __float2int_rn((ty - gy) * sy);
    int iz = __float2int_rn((tz - gz) * sz);
    ix = min(max(ix, 0), Rm1);
    iy = min(max(iy, 0), Rm1);
    iz = min(max(iz, 0), Rm1);
    unsigned off = (unsigned)ix * strideX + (unsigned)iy * strideY + (unsigned)iz * 3u;
    float cx = __ldg(grid + off);
    float cy = __ldg(grid + off + 1u);
    float cz = __ldg(grid + off + 2u);
    float dx = tx - cx, dy = ty - cy, dz = tz - cz;
    return sqrtf(fmaf(dx, dx, fmaf(dy, dy, dz * dz)));
}

// ---------------------------------------------------------------------------
// Main kernel: 1 point/thread, 6 transforms + gathers, block reduce, atomic.
// High occupancy (32 regs) — latency hidden by warp count.
// ---------------------------------------------------------------------------
__global__ void __launch_bounds__(256)
main_kernel(const float* __restrict__ pts,
            const float* __restrict__ planes,
            const float* __restrict__ axes,
            const float* __restrict__ grid,
            const float* __restrict__ gmin,
            const float* __restrict__ gmax,
            int N, int R)
{
    int i = blockIdx.x * blockDim.x + threadIdx.x;

    float gx = __ldg(gmin), gy = __ldg(gmin + 1), gz = __ldg(gmin + 2);
    float sx = (float)(R - 1) / (__ldg(gmax)     - gx);
    float sy = (float)(R - 1) / (__ldg(gmax + 1) - gy);
    float sz = (float)(R - 1) / (__ldg(gmax + 2) - gz);
    unsigned strideY = (unsigned)(R * 3);
    unsigned strideX = strideY * (unsigned)R;
    int Rm1 = R - 1;

    float local = 0.f;

    if (i < N) {
        float px = __ldg(pts + 3 * i);
        float py = __ldg(pts + 3 * i + 1);
        float pz = __ldg(pts + 3 * i + 2);

        // Plane reflections
        #pragma unroll
        for (int k = 0; k < 3; k++) {
            float nx = __ldg(planes + k * 4);
            float ny = __ldg(planes + k * 4 + 1);
            float nz = __ldg(planes + k * 4 + 2);
            float d  = __ldg(planes + k * 4 + 3);
            float proj = px * nx + py * ny + pz * nz + d;
            float rx = px - 2.f * proj * nx;
            float ry = py - 2.f * proj * ny;
            float rz = pz - 2.f * proj * nz;
            local += grid_dist(rx, ry, rz, grid, gx, gy, gz, sx, sy, sz, Rm1, strideX, strideY);
        }

        // Quaternion rotations (q NOT normalized — matches reference)
        #pragma unroll
        for (int k = 0; k < 3; k++) {
            float w = __ldg(axes + k * 4);
            float x = __ldg(axes + k * 4 + 1);
            float y = __ldg(axes + k * 4 + 2);
            float z = __ldg(axes + k * 4 + 3);
            // t = q * (0, p)
            float tw = -x * px - y * py - z * pz;
            float qx =  w * px + y * pz - z * py;
            float qy =  w * py - x * pz + z * px;
            float qz =  w * pz + x * py - y * px;
            // r = t * conj(q), vector part
            float rx = -tw * x + qx * w - qy * z + qz * y;
            float ry = -tw * y + qx * z + qy * w - qz * x;
            float rz = -tw * z - qx * y + qy * x + qz * w;
            local += grid_dist(rx, ry, rz, grid, gx, gy, gz, sx, sy, sz, Rm1, strideX, strideY);
        }
    }

    // Warp reduce
    #pragma unroll
    for (int off = 16; off > 0; off >>= 1)
        local += __shfl_down_sync(0xFFFFFFFFu, local, off);

    // Block reduce
    __shared__ float warp_sums[8];
    int lane = threadIdx.x & 31;
    int wid  = threadIdx.x >> 5;
    if (lane == 0) warp_sums[wid] = local;
    __syncthreads();
    if (wid == 0) {
        float s = (lane < (blockDim.x >> 5)) ? warp_sums[lane] : 0.f;
        #pragma unroll
        for (int off = 4; off > 0; off >>= 1)
            s += __shfl_down_sync(0xFFFFFFFFu, s, off);
        if (lane == 0)
            atomicAdd(&g_sum, (double)s);
    }
}

// ---------------------------------------------------------------------------
// Finalize (1 thread): regularizer + outputs + reset accumulator for replay.
// ---------------------------------------------------------------------------
__global__ void finalize_kernel(const float* __restrict__ planes,
                                const float* __restrict__ axes,
                                float* __restrict__ out,
                                int out_size, int N)
{
    double total = g_sum;
    g_sum = 0.0;   // reset for next graph replay

    // A = n n^T - I ; B = v v^T - I, v = normalize(axes[:,1:]) with max(norm,1e-12)
    float n[3][3], v[3][3];
    #pragma unroll
    for (int r = 0; r < 3; r++) {
        #pragma unroll
        for (int c = 0; c < 3; c++)
            n[r][c] = planes[r * 4 + c];
        float x = axes[r * 4 + 1];
        float y = axes[r * 4 + 2];
        float z = axes[r * 4 + 3];
        float nrm = sqrtf(x * x + y * y + z * z);
        float inv = 1.f / fmaxf(nrm, 1e-12f);
        v[r][0] = x * inv; v[r][1] = y * inv; v[r][2] = z * inv;
    }
    float sumA2 = 0.f, sumB2 = 0.f;
    #pragma unroll
    for (int r = 0; r < 3; r++)
        #pragma unroll
        for (int c = 0; c < 3; c++) {
            float da = n[r][0] * n[c][0] + n[r][1] * n[c][1] + n[r][2] * n[c][2]
                     - (r == c ? 1.f : 0.f);
            float db = v[r][0] * v[c][0] + v[r][1] * v[c][1] + v[r][2] * v[c][2]
                     - (r == c ? 1.f : 0.f);
            sumA2 += da * da;
            sumB2 += db * db;
        }

    float loss_r = sumA2 + sumB2;
    float sd  = (float)(total / (double)N);
    float fin = sd + 25.0f * loss_r;
    out[0] = fin;
    if (out_size > 1) out[1] = sd;
    if (out_size > 2) out[2] = loss_r;
}

// ---------------------------------------------------------------------------
extern "C" void kernel_launch(void* const* d_in, const int* in_sizes, int n_in,
                              void* d_out, int out_size)
{
    const float* planes = (const float*)d_in[0];   // (1,3,4)
    const float* axes   = (const float*)d_in[1];   // (1,3,4)
    const float* pts    = (const float*)d_in[2];   // (N,3)
    const float* grid   = (const float*)d_in[3];   // (R,R,R,3)
    const float* gmin   = (const float*)d_in[4];   // (3,)
    const float* gmax   = (const float*)d_in[5];   // (3,)

    int N = in_sizes[2] / 3;
    long gelems = (long)in_sizes[3] / 3;
    int R = (int)llrintf(cbrtf((float)gelems));

    int threads = 256;
    int blocks = (N + threads - 1) / threads;
    main_kernel<<<blocks, threads>>>(pts, planes, axes, grid, gmin, gmax, N, R);
    finalize_kernel<<<1, 1>>>(planes, axes, (float*)d_out, out_size, N);
}